// round 1
// baseline (speedup 1.0000x reference)
#include <cuda_runtime.h>
#include <cstdint>

// ---------------- problem constants ----------------
#define E       256
#define NB      4
#define NTOK    3136            // 16 * 14 * 14
#define MTOT    (NB*NTOK)       // 12544
#define KCONV   2304            // 3 * 3 * 16 * 16
#define THRESH  1.5f

// ---------------- GEMM tiling ----------------
#define TILE_M  64
#define TILE_N  128
#define KC      16
#define ASTRIDE 68              // padded A smem stride (floats)

typedef unsigned long long ull;

// ---------------- device scratch (static allocation only) ----------------
__device__ float g_wTconv[KCONV*E];     // conv weights transposed [k][oc]
__device__ float g_wT[7][E*E];          // 0:wk 1:wv 2:Wki 3:Wvi 4:outproj 5:dense 6:bproj  [k][n]
__device__ float g_q0add[E];
__device__ float g_buf0[MTOT*E];        // tokens -> attn
__device__ float g_buf1[MTOT*E];        // kbuf  -> t1
__device__ float g_buf2[MTOT*E];        // vbuf  -> t2
__device__ float g_buf3[MTOT*E];        // kp
__device__ float g_buf4[MTOT*E];        // vp
__device__ float g_scores[NTOK*NB*4];   // [n][b][h]
__device__ int   g_boundary[NTOK];
__device__ int   g_segstart[NTOK+2];
__device__ int   g_nseg;
__device__ float g_qp[E];

__device__ __forceinline__ float* bufsel(int id){
    switch(id){
        case 0: return g_buf0; case 1: return g_buf1; case 2: return g_buf2;
        case 3: return g_buf3; default: return g_buf4;
    }
}

// ---------------- block reductions (256 threads) ----------------
__device__ __forceinline__ float blockReduceSum(float v, float* red){
    #pragma unroll
    for(int o=16;o;o>>=1) v += __shfl_xor_sync(0xffffffffu, v, o);
    int w = threadIdx.x >> 5, l = threadIdx.x & 31;
    if(l==0) red[w] = v;
    __syncthreads();
    if(w==0){
        float x = (l < 8) ? red[l] : 0.f;
        #pragma unroll
        for(int o=4;o;o>>=1) x += __shfl_xor_sync(0xffffffffu, x, o);
        if(l==0) red[8] = x;
    }
    __syncthreads();
    float r = red[8];
    __syncthreads();
    return r;
}

__device__ __forceinline__ float blockReduceMax(float v, float* red){
    #pragma unroll
    for(int o=16;o;o>>=1) v = fmaxf(v, __shfl_xor_sync(0xffffffffu, v, o));
    int w = threadIdx.x >> 5, l = threadIdx.x & 31;
    if(l==0) red[w] = v;
    __syncthreads();
    if(w==0){
        float x = (l < 8) ? red[l] : -3.402823466e38f;
        #pragma unroll
        for(int o=4;o;o>>=1) x = fmaxf(x, __shfl_xor_sync(0xffffffffu, x, o));
        if(l==0) red[8] = x;
    }
    __syncthreads();
    float r = red[8];
    __syncthreads();
    return r;
}

// ---------------- packed f32x2 inner product core ----------------
__device__ __forceinline__ float2 unpack2(ull v){
    float2 r;
    r.x = __uint_as_float((unsigned)(v & 0xffffffffull));
    r.y = __uint_as_float((unsigned)(v >> 32));
    return r;
}

__device__ __forceinline__ void mm_inner(const float* As, const float* Bs,
                                         int tm_, int tn_, ull acc[4][4]){
    #pragma unroll
    for(int k=0;k<KC;k++){
        float4 av = *(const float4*)(As + k*ASTRIDE + tm_*4);
        ulonglong2 b0 = *(const ulonglong2*)(Bs + k*TILE_N + tn_*8);
        ulonglong2 b1 = *(const ulonglong2*)(Bs + k*TILE_N + tn_*8 + 4);
        ull ad0, ad1, ad2, ad3;
        asm("mov.b64 %0,{%1,%1};" : "=l"(ad0) : "f"(av.x));
        asm("mov.b64 %0,{%1,%1};" : "=l"(ad1) : "f"(av.y));
        asm("mov.b64 %0,{%1,%1};" : "=l"(ad2) : "f"(av.z));
        asm("mov.b64 %0,{%1,%1};" : "=l"(ad3) : "f"(av.w));
        ull bb0 = b0.x, bb1 = b0.y, bb2 = b1.x, bb3 = b1.y;
        #pragma unroll
        for(int i=0;i<4;i++){
            ull a = (i==0)?ad0:(i==1)?ad1:(i==2)?ad2:ad3;
            asm("fma.rn.f32x2 %0, %1, %2, %0;" : "+l"(acc[i][0]) : "l"(a), "l"(bb0));
            asm("fma.rn.f32x2 %0, %1, %2, %0;" : "+l"(acc[i][1]) : "l"(a), "l"(bb1));
            asm("fma.rn.f32x2 %0, %1, %2, %0;" : "+l"(acc[i][2]) : "l"(a), "l"(bb2));
            asm("fma.rn.f32x2 %0, %1, %2, %0;" : "+l"(acc[i][3]) : "l"(a), "l"(bb3));
        }
    }
}

// ---------------- prep: transpose weights ----------------
__global__ void prep_kernel(const float* __restrict__ conv_w,
                            const float* __restrict__ wk, const float* __restrict__ wv,
                            const float* __restrict__ ipw,
                            const float* __restrict__ outp, const float* __restrict__ dense,
                            const float* __restrict__ bproj, const float* __restrict__ gq){
    int idx = blockIdx.x*blockDim.x + threadIdx.x;
    int stride = gridDim.x*blockDim.x;
    for(int i=idx;i<KCONV*E;i+=stride){
        int kk = i >> 8, oc = i & 255;
        g_wTconv[i] = conv_w[oc*KCONV + kk];
    }
    for(int i=idx;i<E*E;i+=stride){
        int k = i >> 8, n = i & 255;
        g_wT[0][i] = wk[n*E + k];
        g_wT[1][i] = wv[n*E + k];
        g_wT[2][i] = ipw[(E   + n)*E + k];
        g_wT[3][i] = ipw[(2*E + n)*E + k];
        g_wT[4][i] = outp[n*E + k];
        g_wT[5][i] = dense[n*E + k];
        g_wT[6][i] = bproj[n*E + k];
    }
    for(int i=idx;i<E;i+=stride) g_q0add[i] = gq[i];
}

// ---------------- conv as implicit GEMM -> tokens (buf0) ----------------
__global__ __launch_bounds__(256) void conv_kernel(const float* __restrict__ video,
                                                   const float* __restrict__ conv_b){
    __shared__ __align__(16) float As[KC*ASTRIDE];
    __shared__ __align__(16) float Bs[KC*TILE_N];
    int tid = threadIdx.x;
    int m0 = blockIdx.x*TILE_M;
    int n0 = blockIdx.y*TILE_N;
    int tn_ = tid & 15, tm_ = tid >> 4;
    int kw = tid & 15, mlb = tid >> 4;

    int dpass[4]; int basep[4];
    #pragma unroll
    for(int p=0;p<4;p++){
        int m = m0 + mlb + p*16;
        int b = m / NTOK; int n = m % NTOK;
        int d = n / 196; int r = n % 196; int h = r / 14; int w = r % 14;
        dpass[p] = d;
        basep[p] = (b*3)*32*50176 + (h*16)*224 + w*16 + kw;
    }

    ull acc[4][4];
    #pragma unroll
    for(int i=0;i<4;i++)
        #pragma unroll
        for(int j=0;j<4;j++) acc[i][j] = 0ull;

    for(int kb=0;kb<KCONV;kb+=KC){
        int c  = kb / 768;
        int rr = kb % 768;
        int kd = rr >> 8;
        int kh = (rr & 255) >> 4;
        #pragma unroll
        for(int p=0;p<4;p++){
            int din = 2*dpass[p] - 1 + kd;
            float v = 0.f;
            if(din >= 0 && din < 32)
                v = video[basep[p] + (c*32 + din)*50176 + kh*224];
            As[kw*ASTRIDE + mlb + p*16] = v;
        }
        {
            int nl = (tid & 31)*4, klb = tid >> 5;
            #pragma unroll
            for(int p=0;p<2;p++){
                int kl = klb + p*8;
                *(float4*)&Bs[kl*TILE_N + nl] = *(const float4*)&g_wTconv[(kb+kl)*E + n0 + nl];
            }
        }
        __syncthreads();
        mm_inner(As, Bs, tm_, tn_, acc);
        __syncthreads();
    }
    // epilogue: + bias, relu
    #pragma unroll
    for(int i=0;i<4;i++){
        int m = m0 + tm_*4 + i;
        #pragma unroll
        for(int j=0;j<4;j++){
            int n = n0 + tn_*8 + j*2;
            float2 r = unpack2(acc[i][j]);
            r.x = fmaxf(r.x + conv_b[n],   0.f);
            r.y = fmaxf(r.y + conv_b[n+1], 0.f);
            *(float2*)&g_buf0[(size_t)m*E + n] = r;
        }
    }
}

// ---------------- generic GEMM: C = A @ Bt + bias (+q0 / mask) ----------------
__global__ __launch_bounds__(256) void gemm_kernel(int aId, int wsel,
                                                   const float* __restrict__ bias,
                                                   int cId, float* __restrict__ Cext,
                                                   int epimode){
    __shared__ __align__(16) float As[KC*ASTRIDE];
    __shared__ __align__(16) float Bs[KC*TILE_N];
    const float* A  = bufsel(aId);
    const float* Bt = g_wT[wsel];
    float* C = (cId >= 0) ? bufsel(cId) : Cext;
    int tid = threadIdx.x;
    int m0 = blockIdx.x*TILE_M;
    int n0 = blockIdx.y*TILE_N;
    int tn_ = tid & 15, tm_ = tid >> 4;
    int kw = tid & 15, mlb = tid >> 4;

    ull acc[4][4];
    #pragma unroll
    for(int i=0;i<4;i++)
        #pragma unroll
        for(int j=0;j<4;j++) acc[i][j] = 0ull;

    for(int kb=0;kb<E;kb+=KC){
        #pragma unroll
        for(int p=0;p<4;p++)
            As[kw*ASTRIDE + mlb + p*16] = A[(size_t)(m0 + mlb + p*16)*E + kb + kw];
        {
            int nl = (tid & 31)*4, klb = tid >> 5;
            #pragma unroll
            for(int p=0;p<2;p++){
                int kl = klb + p*8;
                *(float4*)&Bs[kl*TILE_N + nl] = *(const float4*)&Bt[(kb+kl)*E + n0 + nl];
            }
        }
        __syncthreads();
        mm_inner(As, Bs, tm_, tn_, acc);
        __syncthreads();
    }

    int nseg = (epimode == 2) ? g_nseg : 0;
    #pragma unroll
    for(int i=0;i<4;i++){
        int m = m0 + tm_*4 + i;
        int srow = m % NTOK;
        #pragma unroll
        for(int j=0;j<4;j++){
            int n = n0 + tn_*8 + j*2;
            float2 r = unpack2(acc[i][j]);
            r.x += bias[n];
            r.y += bias[n+1];
            if(epimode == 1){ r.x += g_q0add[n]; r.y += g_q0add[n+1]; }
            if(epimode == 2 && srow >= nseg){ r.x = 0.f; r.y = 0.f; }
            *(float2*)&C[(size_t)m*E + n] = r;
        }
    }
}

// ---------------- row LayerNorm (in place) ----------------
__global__ void ln_kernel(int bufId, const float* __restrict__ g, const float* __restrict__ b){
    __shared__ float red[9];
    float* X = bufsel(bufId) + (size_t)blockIdx.x*E;
    int c = threadIdx.x;
    float v = X[c];
    float mean = blockReduceSum(v, red) * (1.f/E);
    float dd = v - mean;
    float var = blockReduceSum(dd*dd, red) * (1.f/E);
    X[c] = dd * rsqrtf(var + 1e-5f) * g[c] + b[c];
}

// ---------------- byte -> entropy -> boundary ----------------
__global__ void byte_ent_kernel(const float* __restrict__ table){
    __shared__ float red[9];
    int n = blockIdx.x, c = threadIdx.x;
    float v = g_buf0[(size_t)n*E + c];          // batch 0 tokens
    float mean = blockReduceSum(v, red) * (1.f/256.f);
    int byte = (int)rintf(mean * 255.f);
    byte = min(255, max(0, byte));
    float l = table[byte*256 + c];
    float mx = blockReduceMax(l, red);
    float e = expf(l - mx);
    float s = blockReduceSum(e, red);
    float p = e / s;
    float t = -p * log2f(p + 1e-9f);
    float ent = blockReduceSum(t, red);
    if(c == 0) g_boundary[n] = (ent > THRESH) ? 1 : 0;
}

// ---------------- prefix scan -> segment starts ----------------
__global__ void scan_kernel(){
    __shared__ int sm[1024];
    int tid = threadIdx.x;
    int base = tid*4;
    int v[4]; int sum = 0;
    #pragma unroll
    for(int i=0;i<4;i++){
        int idx = base + i;
        int bb = (idx < NTOK) ? g_boundary[idx] : 0;
        v[i] = sum; sum += bb;
    }
    sm[tid] = sum;
    __syncthreads();
    for(int off=1; off<1024; off<<=1){
        int t = (tid >= off) ? sm[tid-off] : 0;
        __syncthreads();
        sm[tid] += t;
        __syncthreads();
    }
    int prev = (tid > 0) ? sm[tid-1] : 0;
    if(tid == 0) g_segstart[0] = 0;
    #pragma unroll
    for(int i=0;i<4;i++){
        int idx = base + i;
        if(idx < NTOK){
            int sg = prev + v[i];                    // exclusive prefix = seg id
            if(g_boundary[idx]) g_segstart[sg + 1] = idx + 1;
            if(idx == NTOK-1){
                g_nseg = sg + 1;
                g_segstart[sg + 1] = NTOK;           // sentinel
            }
        }
    }
}

// ---------------- query path (tiny) ----------------
__global__ void qp_kernel(const float* __restrict__ gq,
                          const float* __restrict__ wq_w, const float* __restrict__ wq_b,
                          const float* __restrict__ lnq_g, const float* __restrict__ lnq_b,
                          const float* __restrict__ ipw, const float* __restrict__ ipb){
    __shared__ float red[9];
    __shared__ float q0s[E];
    __shared__ float qln[E];
    int c = threadIdx.x;
    q0s[c] = gq[c];
    __syncthreads();
    float y = wq_b[c];
    for(int k=0;k<E;k++) y += wq_w[c*E + k]*q0s[k];
    float mean = blockReduceSum(y, red) * (1.f/E);
    float dd = y - mean;
    float var = blockReduceSum(dd*dd, red) * (1.f/E);
    qln[c] = dd * rsqrtf(var + 1e-5f) * lnq_g[c] + lnq_b[c];
    __syncthreads();
    float z = ipb[c];
    for(int k=0;k<E;k++) z += ipw[c*E + k]*qln[k];
    g_qp[c] = z * 0.125f;       // dh^-0.5 = 1/8
}

// ---------------- scores[n][b][h] = qp[h] . kp[b,n,h] ----------------
__global__ void scores_kernel(){
    int wid = threadIdx.x >> 5, lane = threadIdx.x & 31;
    int m = blockIdx.x*8 + wid;
    int b = m / NTOK, n = m % NTOK;
    const float* kr = g_buf3 + (size_t)m*E;     // kp
    #pragma unroll
    for(int h=0;h<4;h++){
        float s = g_qp[h*64 + lane]      * kr[h*64 + lane]
                + g_qp[h*64 + lane + 32] * kr[h*64 + lane + 32];
        #pragma unroll
        for(int o=16;o;o>>=1) s += __shfl_xor_sync(0xffffffffu, s, o);
        if(lane == 0) g_scores[n*16 + b*4 + h] = s;
    }
}

// ---------------- segment softmax-attention -> attn (buf0) ----------------
__global__ void seg_attn_kernel(){
    int s = blockIdx.x, b = blockIdx.y;
    int h = threadIdx.x >> 6, d = threadIdx.x & 63;
    int nseg = g_nseg;
    float* outp = g_buf0 + ((size_t)b*NTOK + s)*E;
    if(s >= nseg){ outp[threadIdx.x] = 0.f; return; }
    int st = g_segstart[s], en = g_segstart[s+1];
    float mx = -3.402823466e38f;
    for(int n=st;n<en;n++) mx = fmaxf(mx, g_scores[n*16 + b*4 + h]);
    float ws = 0.f, acc = 0.f;
    const float* vpb = g_buf4 + ((size_t)b*NTOK)*E + h*64 + d;   // vp
    for(int n=st;n<en;n++){
        float wv = expf(g_scores[n*16 + b*4 + h] - mx);
        ws += wv;
        acc += wv * vpb[(size_t)n*E];
    }
    outp[h*64 + d] = acc / ws;
}

// ---------------- launch ----------------
extern "C" void kernel_launch(void* const* d_in, const int* in_sizes, int n_in,
                              void* d_out, int out_size){
    const float* video     = (const float*)d_in[0];
    const float* conv_w    = (const float*)d_in[1];
    const float* conv_b    = (const float*)d_in[2];
    const float* wq_w      = (const float*)d_in[3];
    const float* wq_b      = (const float*)d_in[4];
    const float* wk_w      = (const float*)d_in[5];
    const float* wk_b      = (const float*)d_in[6];
    const float* wv_w      = (const float*)d_in[7];
    const float* wv_b      = (const float*)d_in[8];
    const float* lnq_g     = (const float*)d_in[9];
    const float* lnq_b     = (const float*)d_in[10];
    const float* lnk_g     = (const float*)d_in[11];
    const float* lnk_b     = (const float*)d_in[12];
    const float* lnv_g     = (const float*)d_in[13];
    const float* lnv_b     = (const float*)d_in[14];
    const float* in_proj_w = (const float*)d_in[15];
    const float* in_proj_b = (const float*)d_in[16];
    const float* out_proj_w= (const float*)d_in[17];
    const float* out_proj_b= (const float*)d_in[18];
    const float* dense_w   = (const float*)d_in[19];
    const float* dense_b   = (const float*)d_in[20];
    const float* bproj_w   = (const float*)d_in[21];
    const float* bproj_b   = (const float*)d_in[22];
    const float* gq        = (const float*)d_in[23];
    const float* ent_table = (const float*)d_in[24];
    float* out = (float*)d_out;

    dim3 gg(MTOT/TILE_M, E/TILE_N);   // (196, 2)

    prep_kernel<<<512,256>>>(conv_w, wk_w, wv_w, in_proj_w, out_proj_w, dense_w, bproj_w, gq);
    conv_kernel<<<gg,256>>>(video, conv_b);                         // -> buf0 (tokens)
    byte_ent_kernel<<<NTOK,256>>>(ent_table);
    scan_kernel<<<1,1024>>>();
    qp_kernel<<<1,256>>>(gq, wq_w, wq_b, lnq_g, lnq_b, in_proj_w, in_proj_b);

    gemm_kernel<<<gg,256>>>(0, 0, wk_b,          1, nullptr, 0);    // tokens @ wk  -> buf1
    ln_kernel<<<MTOT,256>>>(1, lnk_g, lnk_b);
    gemm_kernel<<<gg,256>>>(0, 1, wv_b,          2, nullptr, 0);    // tokens @ wv  -> buf2
    ln_kernel<<<MTOT,256>>>(2, lnv_g, lnv_b);
    gemm_kernel<<<gg,256>>>(1, 2, in_proj_b+E,   3, nullptr, 0);    // k @ Wki -> kp (buf3)
    gemm_kernel<<<gg,256>>>(2, 3, in_proj_b+2*E, 4, nullptr, 0);    // v @ Wvi -> vp (buf4)

    scores_kernel<<<MTOT/8,256>>>();
    seg_attn_kernel<<<dim3(NTOK,NB),256>>>();                       // -> buf0 (attn)

    gemm_kernel<<<gg,256>>>(0, 4, out_proj_b,    1, nullptr, 0);    // attn @ outproj -> buf1
    gemm_kernel<<<gg,256>>>(1, 5, dense_b,       2, nullptr, 1);    // @ dense + q0   -> buf2
    gemm_kernel<<<gg,256>>>(2, 6, bproj_b,      -1, out,     2);    // @ bproj, mask  -> out
}